// round 10
// baseline (speedup 1.0000x reference)
#include <cuda_runtime.h>
#include <cuda_bf16.h>
#include <mma.h>
#include <math.h>
#include <stdint.h>

using namespace nvcuda;

#define NB 64
#define TT 1024
#define DD 1024
#define HH 1024
#define K4 4096
#define NCTA_REC 128
#define KC 64          // K-chunk (elements)
#define PE 72          // smem pitch for bf16 tiles (elements)
#define GP 68          // smem pitch for fp32 staging (elements)

// ---------------- device globals ----------------
__device__ float g_xW[(size_t)TT * K4 * NB];          // [t][k'][n]
__device__ __nv_bfloat16 g_WhT_hi[(size_t)K4 * HH];   // [k'][j]
__device__ __nv_bfloat16 g_WhT_lo[(size_t)K4 * HH];
__device__ __nv_bfloat16 g_WxT_hi[(size_t)K4 * DD];   // [k'][d]
__device__ __nv_bfloat16 g_WxT_lo[(size_t)K4 * DD];
__device__ __nv_bfloat16 g_xh[(size_t)NB * TT * DD];  // [n][t][d]
__device__ __nv_bfloat16 g_xl[(size_t)NB * TT * DD];
__device__ __nv_bfloat16 g_hh[2][(size_t)NB * HH];    // [buf][n][j]
__device__ __nv_bfloat16 g_hl[2][(size_t)NB * HH];
__device__ unsigned int g_bar_count;
__device__ unsigned int g_bar_gen;

__device__ __forceinline__ float sigf(float v) { return 1.0f / (1.0f + __expf(-v)); }
// fast tanh via __expf; clamp so e^{2x} stays finite
__device__ __forceinline__ float tanhf_fast(float v) {
    float x = fminf(fmaxf(v, -15.0f), 15.0f);
    float e = __expf(2.0f * x);
    return (e - 1.0f) / (e + 1.0f);
}

// ---------------------------------------------------------------------------
// Preps
// ---------------------------------------------------------------------------
__global__ void xsplit_kernel(const float* __restrict__ x) {
    size_t i = (size_t)blockIdx.x * 256 + threadIdx.x;   // 64M
    float v = x[i];
    __nv_bfloat16 h = __float2bfloat16(v);
    g_xh[i] = h;
    g_xl[i] = __float2bfloat16(v - __bfloat162float(h));
}

// W[j][k] (1024 x 4096) -> WT_hi/lo[k'][j], k' = (jout>>3)*32 + gate*8 + (jout&7)
// which selects destination in DEVICE code (host-side __device__ symbol args
// were the R5-R8 zero-output bug).
__global__ void wprep_kernel(const float* __restrict__ W, int which) {
    __nv_bfloat16* __restrict__ dhi = which ? g_WhT_hi : g_WxT_hi;
    __nv_bfloat16* __restrict__ dlo = which ? g_WhT_lo : g_WxT_lo;
    const int k0 = blockIdx.x * 32;
    const int j0 = blockIdx.y * 32;
    __shared__ float tile[32][33];
    const int tid = threadIdx.x;
    const int jj = tid >> 5, kk = tid & 31;
    #pragma unroll
    for (int p = 0; p < 4; p++)
        tile[jj + 8 * p][kk] = W[(size_t)(j0 + jj + 8 * p) * K4 + k0 + kk];
    __syncthreads();
    const int r = tid >> 3, j4 = (tid & 7) * 4;
    const int korig = k0 + r;
    const int gate = korig >> 10, jout = korig & 1023;
    const int kp = (jout >> 3) * 32 + gate * 8 + (jout & 7);
    __nv_bfloat16 hi4[4], lo4[4];
    #pragma unroll
    for (int u = 0; u < 4; u++) {
        float v = tile[j4 + u][r];
        __nv_bfloat16 h = __float2bfloat16(v);
        hi4[u] = h;
        lo4[u] = __float2bfloat16(v - __bfloat162float(h));
    }
    size_t o = (size_t)kp * HH + j0 + j4;
    *(uint2*)&dhi[o] = *(uint2*)hi4;
    *(uint2*)&dlo[o] = *(uint2*)lo4;
}

__global__ void init_kernel(const float* __restrict__ h0) {
    int i = blockIdx.x * 256 + threadIdx.x;   // 65536, [n][j]
    float v = h0[i];
    __nv_bfloat16 h = __float2bfloat16(v);
    g_hh[0][i] = h;
    g_hl[0][i] = __float2bfloat16(v - __bfloat162float(h));
    if (i == 0) { g_bar_count = 0; g_bar_gen = 0; }
}

// ---------------------------------------------------------------------------
// GEMM inner machinery. CTA tile: 32 k'-rows (m) x 64 n; warps 2(m) x 4(n).
// 3-term bf16 split into THREE INDEPENDENT accumulators (fa0/fa1/fa2) so the
// HMMA stream has 3 parallel dependency chains instead of 1 (R9 was
// latency-serialized on a single accumulator chain).
// ---------------------------------------------------------------------------
#define WMMA_COMPUTE(sAh_, sAl_, sBh_, sBl_, fa0_, fa1_, fa2_)                   \
    _Pragma("unroll")                                                            \
    for (int ks = 0; ks < 4; ks++) {                                             \
        wmma::fragment<wmma::matrix_a, 16, 16, 16, __nv_bfloat16, wmma::row_major> fah, fal; \
        wmma::fragment<wmma::matrix_b, 16, 16, 16, __nv_bfloat16, wmma::col_major> fbh, fbl; \
        wmma::load_matrix_sync(fah, sAh_ + wm * 16 * PE + ks * 16, PE);          \
        wmma::load_matrix_sync(fal, sAl_ + wm * 16 * PE + ks * 16, PE);          \
        wmma::load_matrix_sync(fbh, sBh_ + wn * 16 * PE + ks * 16, PE);          \
        wmma::load_matrix_sync(fbl, sBl_ + wn * 16 * PE + ks * 16, PE);          \
        wmma::mma_sync(fa0_, fah, fbh, fa0_);                                    \
        wmma::mma_sync(fa1_, fal, fbh, fa1_);                                    \
        wmma::mma_sync(fa2_, fah, fbl, fa2_);                                    \
    }

// ---------------------------------------------------------------------------
// Phase 1: g_xW[t][k'][n] = x @ Wx + b
// ---------------------------------------------------------------------------
__global__ __launch_bounds__(256) void phase1_wmma(const float* __restrict__ b) {
    __shared__ __nv_bfloat16 sAh[32 * PE], sAl[32 * PE];
    __shared__ __nv_bfloat16 sBh[64 * PE], sBl[64 * PE];
    __shared__ float ssm[32 * GP];
    const int tid = threadIdx.x;
    const int w = tid >> 5, wm = w >> 2, wn = w & 3;
    const int cta = blockIdx.x;       // k' block (0..127)
    const int t = blockIdx.y;

    const int arow = tid >> 3, aseg = tid & 7;
    const __nv_bfloat16* aph = g_WxT_hi + (size_t)(cta * 32 + arow) * DD + aseg * 8;
    const __nv_bfloat16* apl = g_WxT_lo + (size_t)(cta * 32 + arow) * DD + aseg * 8;
    const __nv_bfloat16* bph = g_xh + ((size_t)arow * TT + t) * DD + aseg * 8;
    const __nv_bfloat16* bpl = g_xl + ((size_t)arow * TT + t) * DD + aseg * 8;
    const size_t brs = (size_t)32 * TT * DD;    // +32 n rows
    const int sA = arow * PE + aseg * 8;
    const int sB0 = arow * PE + aseg * 8;
    const int sB1 = (arow + 32) * PE + aseg * 8;

    wmma::fragment<wmma::accumulator, 16, 16, 16, float> fa0, fa1, fa2;
    wmma::fill_fragment(fa0, 0.0f);
    wmma::fill_fragment(fa1, 0.0f);
    wmma::fill_fragment(fa2, 0.0f);

    uint4 rAh, rAl, rBh0, rBh1, rBl0, rBl1;
    rAh = *(const uint4*)(aph);        rAl = *(const uint4*)(apl);
    rBh0 = *(const uint4*)(bph);       rBh1 = *(const uint4*)(bph + brs);
    rBl0 = *(const uint4*)(bpl);       rBl1 = *(const uint4*)(bpl + brs);

    for (int c = 0; c < 16; c++) {
        __syncthreads();
        *(uint4*)&sAh[sA] = rAh;   *(uint4*)&sAl[sA] = rAl;
        *(uint4*)&sBh[sB0] = rBh0; *(uint4*)&sBh[sB1] = rBh1;
        *(uint4*)&sBl[sB0] = rBl0; *(uint4*)&sBl[sB1] = rBl1;
        __syncthreads();
        if (c < 15) {
            const int o = (c + 1) * KC;
            rAh = *(const uint4*)(aph + o);        rAl = *(const uint4*)(apl + o);
            rBh0 = *(const uint4*)(bph + o);       rBh1 = *(const uint4*)(bph + brs + o);
            rBl0 = *(const uint4*)(bpl + o);       rBl1 = *(const uint4*)(bpl + brs + o);
        }
        WMMA_COMPUTE(sAh, sAl, sBh, sBl, fa0, fa1, fa2)
    }

    #pragma unroll
    for (int i = 0; i < fa0.num_elements; i++) fa0.x[i] += fa1.x[i] + fa2.x[i];
    wmma::store_matrix_sync(ssm + wm * 16 * GP + wn * 16, fa0, GP, wmma::mem_row_major);
    __syncthreads();

    float* xwo = g_xW + ((size_t)t * K4 + cta * 32) * 64;
    #pragma unroll
    for (int u = 0; u < 8; u++) {
        const int idx = tid + 256 * u;
        const int lm = idx >> 6, n = idx & 63;
        const int korig = (lm >> 3) * 1024 + cta * 8 + (lm & 7);
        xwo[idx] = ssm[lm * GP + n] + __ldg(&b[korig]);
    }
}

// ---------------------------------------------------------------------------
// Persistent recurrence (wmma). 128 CTAs, grid barrier per step.
// ---------------------------------------------------------------------------
__global__ __launch_bounds__(256, 1) void rec_wmma(float* __restrict__ out) {
    __shared__ __nv_bfloat16 sAh[32 * PE], sAl[32 * PE];
    __shared__ __nv_bfloat16 sBh[64 * PE], sBl[64 * PE];
    __shared__ float gsm[32 * GP];
    __shared__ float csm[8 * GP];
    const int tid = threadIdx.x;
    const int w = tid >> 5, wm = w >> 2, wn = w & 3;
    const int cta = blockIdx.x;

    const int arow = tid >> 3, aseg = tid & 7;
    const __nv_bfloat16* aph = g_WhT_hi + (size_t)(cta * 32 + arow) * HH + aseg * 8;
    const __nv_bfloat16* apl = g_WhT_lo + (size_t)(cta * 32 + arow) * HH + aseg * 8;
    const size_t bo0 = (size_t)arow * HH + aseg * 8;          // n = arow
    const size_t bo1 = (size_t)(arow + 32) * HH + aseg * 8;   // n = arow+32
    const int sA = arow * PE + aseg * 8;
    const int sB0 = arow * PE + aseg * 8;
    const int sB1 = (arow + 32) * PE + aseg * 8;

    for (int i = tid; i < 8 * GP; i += 256) csm[i] = 0.f;
    __syncthreads();

    const int cn = tid >> 2;            // n for combine
    const int jp = (tid & 3) * 2;       // jl pair base

    for (int t = 0; t < TT; t++) {
        const __nv_bfloat16* hhb = g_hh[t & 1];
        const __nv_bfloat16* hlb = g_hl[t & 1];

        // prefetch xW rows for this tile (coalesced; layout [lm][n] = linear)
        const float* xwp = g_xW + ((size_t)t * K4 + cta * 32) * 64;
        float xwr[8];
        #pragma unroll
        for (int u = 0; u < 8; u++) xwr[u] = __ldg(&xwp[tid + 256 * u]);

        wmma::fragment<wmma::accumulator, 16, 16, 16, float> fa0, fa1, fa2;
        wmma::fill_fragment(fa0, 0.0f);
        wmma::fill_fragment(fa1, 0.0f);
        wmma::fill_fragment(fa2, 0.0f);

        uint4 rAh, rAl, rBh0, rBh1, rBl0, rBl1;
        rAh = *(const uint4*)(aph);            rAl = *(const uint4*)(apl);
        rBh0 = *(const uint4*)(hhb + bo0);     rBh1 = *(const uint4*)(hhb + bo1);
        rBl0 = *(const uint4*)(hlb + bo0);     rBl1 = *(const uint4*)(hlb + bo1);

        for (int c = 0; c < 16; c++) {
            __syncthreads();
            *(uint4*)&sAh[sA] = rAh;   *(uint4*)&sAl[sA] = rAl;
            *(uint4*)&sBh[sB0] = rBh0; *(uint4*)&sBh[sB1] = rBh1;
            *(uint4*)&sBl[sB0] = rBl0; *(uint4*)&sBl[sB1] = rBl1;
            __syncthreads();
            if (c < 15) {
                const int o = (c + 1) * KC;
                rAh = *(const uint4*)(aph + o);            rAl = *(const uint4*)(apl + o);
                rBh0 = *(const uint4*)(hhb + bo0 + o);     rBh1 = *(const uint4*)(hhb + bo1 + o);
                rBl0 = *(const uint4*)(hlb + bo0 + o);     rBl1 = *(const uint4*)(hlb + bo1 + o);
            }
            WMMA_COMPUTE(sAh, sAl, sBh, sBl, fa0, fa1, fa2)
        }

        #pragma unroll
        for (int i = 0; i < fa0.num_elements; i++) fa0.x[i] += fa1.x[i] + fa2.x[i];
        wmma::store_matrix_sync(gsm + wm * 16 * GP + wn * 16, fa0, GP, wmma::mem_row_major);
        __syncthreads();

        // activation pass: lm = gate*8 + jl; gate 3 (lm>=24) uses tanh
        #pragma unroll
        for (int u = 0; u < 8; u++) {
            const int idx = tid + 256 * u;
            const int lm = idx >> 6, n = idx & 63;
            const float v = gsm[lm * GP + n] + xwr[u];
            gsm[lm * GP + n] = (lm >= 24) ? tanhf_fast(v) : sigf(v);
        }
        __syncthreads();

        // combine: thread -> (n = cn, jl in {jp, jp+1})
        float hv[2];
        __nv_bfloat16 hh2[2], hl2[2];
        #pragma unroll
        for (int u = 0; u < 2; u++) {
            const int jl = jp + u;
            const float iv = gsm[(jl)      * GP + cn];
            const float fv = gsm[(8 + jl)  * GP + cn];
            const float ov = gsm[(16 + jl) * GP + cn];
            const float gv = gsm[(24 + jl) * GP + cn];
            const float cprev = csm[jl * GP + cn];
            const float cnew = fv * cprev + iv * gv;
            csm[jl * GP + cn] = cnew;
            const float h = ov * tanhf_fast(cnew);
            hv[u] = h;
            const __nv_bfloat16 hb = __float2bfloat16(h);
            hh2[u] = hb;
            hl2[u] = __float2bfloat16(h - __bfloat162float(hb));
        }
        *(float2*)&out[((size_t)cn * TT + t) * HH + cta * 8 + jp] = make_float2(hv[0], hv[1]);
        const int nb = (t + 1) & 1;
        *(uint32_t*)&g_hh[nb][(size_t)cn * HH + cta * 8 + jp] = *(uint32_t*)hh2;
        *(uint32_t*)&g_hl[nb][(size_t)cn * HH + cta * 8 + jp] = *(uint32_t*)hl2;

        // grid barrier (128 CTAs, 1/SM, co-resident)
        __syncthreads();
        if (tid == 0) {
            __threadfence();
            unsigned int ticket = atomicAdd(&g_bar_count, 1);
            if (ticket == NCTA_REC - 1) {
                g_bar_count = 0;
                __threadfence();
                atomicAdd(&g_bar_gen, 1);
            } else {
                while (*(volatile unsigned int*)&g_bar_gen < (unsigned)(t + 1)) { }
            }
            __threadfence();
        }
        __syncthreads();
    }
}

// ---------------------------------------------------------------------------
extern "C" void kernel_launch(void* const* d_in, const int* in_sizes, int n_in,
                              void* d_out, int out_size)
{
    (void)in_sizes; (void)n_in; (void)out_size;
    const float* x  = (const float*)d_in[0];
    const float* h0 = (const float*)d_in[1];
    const float* Wx = (const float*)d_in[2];
    const float* Wh = (const float*)d_in[3];
    const float* b  = (const float*)d_in[4];
    float* out = (float*)d_out;

    xsplit_kernel<<<262144, 256>>>(x);
    wprep_kernel<<<dim3(128, 32), 256>>>(Wx, 0);   // -> g_WxT_hi/lo
    wprep_kernel<<<dim3(128, 32), 256>>>(Wh, 1);   // -> g_WhT_hi/lo
    init_kernel<<<256, 256>>>(h0);
    phase1_wmma<<<dim3(128, 1024), 256>>>(b);
    rec_wmma<<<NCTA_REC, 256>>>(out);
}

// round 11
// speedup vs baseline: 1.2061x; 1.2061x over previous
#include <cuda_runtime.h>
#include <cuda_bf16.h>
#include <mma.h>
#include <math.h>
#include <stdint.h>

using namespace nvcuda;

#define NB 64
#define TT 1024
#define DD 1024
#define HH 1024
#define K4 4096
#define NCTA_REC 128
#define KC 64          // K-chunk (elements)
#define PE 72          // smem pitch for bf16 tiles (elements)
#define GP 68          // smem pitch for fp32 staging (elements)

// ---------------- device globals ----------------
__device__ float g_xW[(size_t)TT * K4 * NB];          // [t][k'][n]
__device__ __nv_bfloat16 g_WhT_hi[(size_t)K4 * HH];   // [k'][j]
__device__ __nv_bfloat16 g_WhT_lo[(size_t)K4 * HH];
__device__ __nv_bfloat16 g_WxT_hi[(size_t)K4 * DD];   // [k'][d]
__device__ __nv_bfloat16 g_WxT_lo[(size_t)K4 * DD];
__device__ __nv_bfloat16 g_xh[(size_t)NB * TT * DD];  // [n][t][d]
__device__ __nv_bfloat16 g_xl[(size_t)NB * TT * DD];
__device__ __nv_bfloat16 g_hh[2][(size_t)NB * HH];    // [buf][n][j]
__device__ __nv_bfloat16 g_hl[2][(size_t)NB * HH];
__device__ unsigned int g_bar_count;
__device__ unsigned int g_bar_gen;

__device__ __forceinline__ float sigf(float v) { return 1.0f / (1.0f + __expf(-v)); }
__device__ __forceinline__ float tanhf_fast(float v) {
    float x = fminf(fmaxf(v, -15.0f), 15.0f);
    float e = __expf(2.0f * x);
    return (e - 1.0f) / (e + 1.0f);
}

// ---------------------------------------------------------------------------
// Preps (unchanged, validated)
// ---------------------------------------------------------------------------
__global__ void xsplit_kernel(const float* __restrict__ x) {
    size_t i = (size_t)blockIdx.x * 256 + threadIdx.x;   // 64M
    float v = x[i];
    __nv_bfloat16 h = __float2bfloat16(v);
    g_xh[i] = h;
    g_xl[i] = __float2bfloat16(v - __bfloat162float(h));
}

__global__ void wprep_kernel(const float* __restrict__ W, int which) {
    __nv_bfloat16* __restrict__ dhi = which ? g_WhT_hi : g_WxT_hi;
    __nv_bfloat16* __restrict__ dlo = which ? g_WhT_lo : g_WxT_lo;
    const int k0 = blockIdx.x * 32;
    const int j0 = blockIdx.y * 32;
    __shared__ float tile[32][33];
    const int tid = threadIdx.x;
    const int jj = tid >> 5, kk = tid & 31;
    #pragma unroll
    for (int p = 0; p < 4; p++)
        tile[jj + 8 * p][kk] = W[(size_t)(j0 + jj + 8 * p) * K4 + k0 + kk];
    __syncthreads();
    const int r = tid >> 3, j4 = (tid & 7) * 4;
    const int korig = k0 + r;
    const int gate = korig >> 10, jout = korig & 1023;
    const int kp = (jout >> 3) * 32 + gate * 8 + (jout & 7);
    __nv_bfloat16 hi4[4], lo4[4];
    #pragma unroll
    for (int u = 0; u < 4; u++) {
        float v = tile[j4 + u][r];
        __nv_bfloat16 h = __float2bfloat16(v);
        hi4[u] = h;
        lo4[u] = __float2bfloat16(v - __bfloat162float(h));
    }
    size_t o = (size_t)kp * HH + j0 + j4;
    *(uint2*)&dhi[o] = *(uint2*)hi4;
    *(uint2*)&dlo[o] = *(uint2*)lo4;
}

__global__ void init_kernel(const float* __restrict__ h0) {
    int i = blockIdx.x * 256 + threadIdx.x;   // 65536, [n][j]
    float v = h0[i];
    __nv_bfloat16 h = __float2bfloat16(v);
    g_hh[0][i] = h;
    g_hl[0][i] = __float2bfloat16(v - __bfloat162float(h));
    if (i == 0) { g_bar_count = 0; g_bar_gen = 0; }
}

// ---------------------------------------------------------------------------
// GEMM core. CTA tile 32 k'-rows (m) x 64 n. 8 warps = 4 (ks-split, q) x 2
// (n-half, p); warp tile 32x32 at its ks -> 8 frag loads per 12 mma
// (half the LDSM traffic of the R9 16x16 layout). Partial sums over q are
// reduced via raw per-lane fragment blobs in smem (layout-agnostic).
// ---------------------------------------------------------------------------
#define ACCX(j) acc[(j) >> 4][((j) >> 3) & 1].x[(j) & 7]

#define WMMA_CHUNK(sAh_, sAl_, sBh_, sBl_)                                       \
    do {                                                                         \
        wmma::fragment<wmma::matrix_a, 16, 16, 16, __nv_bfloat16, wmma::row_major> fah[2], fal[2]; \
        wmma::fragment<wmma::matrix_b, 16, 16, 16, __nv_bfloat16, wmma::col_major> fbh[2], fbl[2]; \
        _Pragma("unroll")                                                        \
        for (int mi = 0; mi < 2; mi++) {                                         \
            wmma::load_matrix_sync(fah[mi], sAh_ + (mi * 16) * PE + q * 16, PE); \
            wmma::load_matrix_sync(fal[mi], sAl_ + (mi * 16) * PE + q * 16, PE); \
        }                                                                        \
        _Pragma("unroll")                                                        \
        for (int ni = 0; ni < 2; ni++) {                                         \
            wmma::load_matrix_sync(fbh[ni], sBh_ + (p * 32 + ni * 16) * PE + q * 16, PE); \
            wmma::load_matrix_sync(fbl[ni], sBl_ + (p * 32 + ni * 16) * PE + q * 16, PE); \
        }                                                                        \
        _Pragma("unroll")                                                        \
        for (int mi = 0; mi < 2; mi++)                                           \
            _Pragma("unroll")                                                    \
            for (int ni = 0; ni < 2; ni++) {                                     \
                wmma::mma_sync(acc[mi][ni], fah[mi], fbh[ni], acc[mi][ni]);      \
                wmma::mma_sync(acc[mi][ni], fal[mi], fbh[ni], acc[mi][ni]);      \
                wmma::mma_sync(acc[mi][ni], fah[mi], fbl[ni], acc[mi][ni]);      \
            }                                                                    \
    } while (0)

#define STORE_BLOB(rsm_, slot_)                                                  \
    do {                                                                         \
        float* bp_ = (rsm_) + (slot_) * 1024 + lane * 4;                         \
        _Pragma("unroll")                                                        \
        for (int e4 = 0; e4 < 8; e4++) {                                         \
            int j_ = e4 * 4;                                                     \
            *(float4*)(bp_ + e4 * 128) =                                         \
                make_float4(ACCX(j_), ACCX(j_ + 1), ACCX(j_ + 2), ACCX(j_ + 3)); \
        }                                                                        \
    } while (0)

#define LOAD_BLOB_ADD(rsm_, slot_)                                               \
    do {                                                                         \
        const float* bp_ = (rsm_) + (slot_) * 1024 + lane * 4;                   \
        _Pragma("unroll")                                                        \
        for (int e4 = 0; e4 < 8; e4++) {                                         \
            int j_ = e4 * 4;                                                     \
            float4 v_ = *(const float4*)(bp_ + e4 * 128);                        \
            ACCX(j_) += v_.x; ACCX(j_ + 1) += v_.y;                              \
            ACCX(j_ + 2) += v_.z; ACCX(j_ + 3) += v_.w;                          \
        }                                                                        \
    } while (0)

// q-reduction: (q2,q3) -> (q0,q1), then q1 -> q0. After this q==0 warps hold
// the full K sum for their (p) n-half.
#define REDUCE_Q(rsm_)                                                           \
    do {                                                                         \
        __syncthreads();                                                         \
        if (q >= 2) STORE_BLOB(rsm_, (q - 2) * 2 + p);                           \
        __syncthreads();                                                         \
        if (q < 2) LOAD_BLOB_ADD(rsm_, q * 2 + p);                               \
        __syncthreads();                                                         \
        if (q == 1) STORE_BLOB(rsm_, p);                                         \
        __syncthreads();                                                         \
        if (q == 0) LOAD_BLOB_ADD(rsm_, p);                                      \
    } while (0)

// ---------------------------------------------------------------------------
// Phase 1: g_xW[t][k'][n] = x @ Wx + b
// ---------------------------------------------------------------------------
__global__ __launch_bounds__(256, 2) void phase1_wmma(const float* __restrict__ b) {
    __shared__ __align__(16) __nv_bfloat16 sAh[32 * PE], sAl[32 * PE];
    __shared__ __align__(16) __nv_bfloat16 sBh[64 * PE], sBl[64 * PE];
    __shared__ float ssm[32 * GP];
    float* rsm = (float*)sAh;    // blob overlay on dead A/B buffers (16KB < 27.6KB)
    const int tid = threadIdx.x;
    const int w = tid >> 5, lane = tid & 31;
    const int q = w >> 1, p = w & 1;
    const int cta = blockIdx.x;       // k' block (0..127)
    const int t = blockIdx.y;

    const int arow = tid >> 3, aseg = tid & 7;
    const __nv_bfloat16* aph = g_WxT_hi + (size_t)(cta * 32 + arow) * DD + aseg * 8;
    const __nv_bfloat16* apl = g_WxT_lo + (size_t)(cta * 32 + arow) * DD + aseg * 8;
    const __nv_bfloat16* bph = g_xh + ((size_t)arow * TT + t) * DD + aseg * 8;
    const __nv_bfloat16* bpl = g_xl + ((size_t)arow * TT + t) * DD + aseg * 8;
    const size_t brs = (size_t)32 * TT * DD;    // +32 n rows
    const int sA = arow * PE + aseg * 8;
    const int sB0 = arow * PE + aseg * 8;
    const int sB1 = (arow + 32) * PE + aseg * 8;

    wmma::fragment<wmma::accumulator, 16, 16, 16, float> acc[2][2];
    #pragma unroll
    for (int mi = 0; mi < 2; mi++)
        #pragma unroll
        for (int ni = 0; ni < 2; ni++) wmma::fill_fragment(acc[mi][ni], 0.0f);

    uint4 rAh, rAl, rBh0, rBh1, rBl0, rBl1;
    rAh = *(const uint4*)(aph);        rAl = *(const uint4*)(apl);
    rBh0 = *(const uint4*)(bph);       rBh1 = *(const uint4*)(bph + brs);
    rBl0 = *(const uint4*)(bpl);       rBl1 = *(const uint4*)(bpl + brs);

    for (int c = 0; c < 16; c++) {
        __syncthreads();
        *(uint4*)&sAh[sA] = rAh;   *(uint4*)&sAl[sA] = rAl;
        *(uint4*)&sBh[sB0] = rBh0; *(uint4*)&sBh[sB1] = rBh1;
        *(uint4*)&sBl[sB0] = rBl0; *(uint4*)&sBl[sB1] = rBl1;
        __syncthreads();
        if (c < 15) {
            const int o = (c + 1) * KC;
            rAh = *(const uint4*)(aph + o);        rAl = *(const uint4*)(apl + o);
            rBh0 = *(const uint4*)(bph + o);       rBh1 = *(const uint4*)(bph + brs + o);
            rBl0 = *(const uint4*)(bpl + o);       rBl1 = *(const uint4*)(bpl + brs + o);
        }
        WMMA_CHUNK(sAh, sAl, sBh, sBl);
    }

    REDUCE_Q(rsm);
    __syncthreads();
    if (q == 0) {
        #pragma unroll
        for (int mi = 0; mi < 2; mi++)
            #pragma unroll
            for (int ni = 0; ni < 2; ni++)
                wmma::store_matrix_sync(ssm + (mi * 16) * GP + p * 32 + ni * 16,
                                        acc[mi][ni], GP, wmma::mem_row_major);
    }
    __syncthreads();

    float* xwo = g_xW + ((size_t)t * K4 + cta * 32) * 64;
    #pragma unroll
    for (int u = 0; u < 8; u++) {
        const int idx = tid + 256 * u;
        const int lm = idx >> 6, n = idx & 63;
        const int korig = (lm >> 3) * 1024 + cta * 8 + (lm & 7);
        xwo[idx] = ssm[lm * GP + n] + __ldg(&b[korig]);
    }
}

// ---------------------------------------------------------------------------
// Persistent recurrence. 128 CTAs, grid barrier per step.
// ---------------------------------------------------------------------------
__global__ __launch_bounds__(256, 1) void rec_wmma(float* __restrict__ out) {
    __shared__ __align__(16) __nv_bfloat16 sAh[32 * PE], sAl[32 * PE];
    __shared__ __align__(16) __nv_bfloat16 sBh[64 * PE], sBl[64 * PE];
    __shared__ float gsm[32 * GP];
    __shared__ float csm[8 * GP];
    float* rsm = (float*)sAh;    // blob overlay (buffers dead during reduction)
    const int tid = threadIdx.x;
    const int w = tid >> 5, lane = tid & 31;
    const int q = w >> 1, p = w & 1;
    const int cta = blockIdx.x;

    const int arow = tid >> 3, aseg = tid & 7;
    const __nv_bfloat16* aph = g_WhT_hi + (size_t)(cta * 32 + arow) * HH + aseg * 8;
    const __nv_bfloat16* apl = g_WhT_lo + (size_t)(cta * 32 + arow) * HH + aseg * 8;
    const size_t bo0 = (size_t)arow * HH + aseg * 8;          // n = arow
    const size_t bo1 = (size_t)(arow + 32) * HH + aseg * 8;   // n = arow+32
    const int sA = arow * PE + aseg * 8;
    const int sB0 = arow * PE + aseg * 8;
    const int sB1 = (arow + 32) * PE + aseg * 8;

    for (int i = tid; i < 8 * GP; i += 256) csm[i] = 0.f;
    __syncthreads();

    const int cn = tid >> 2;            // n for combine
    const int jp = (tid & 3) * 2;       // jl pair base

    for (int t = 0; t < TT; t++) {
        const __nv_bfloat16* hhb = g_hh[t & 1];
        const __nv_bfloat16* hlb = g_hl[t & 1];

        const float* xwp = g_xW + ((size_t)t * K4 + cta * 32) * 64;
        float xwr[8];
        #pragma unroll
        for (int u = 0; u < 8; u++) xwr[u] = __ldg(&xwp[tid + 256 * u]);

        wmma::fragment<wmma::accumulator, 16, 16, 16, float> acc[2][2];
        #pragma unroll
        for (int mi = 0; mi < 2; mi++)
            #pragma unroll
            for (int ni = 0; ni < 2; ni++) wmma::fill_fragment(acc[mi][ni], 0.0f);

        uint4 rAh, rAl, rBh0, rBh1, rBl0, rBl1;
        rAh = *(const uint4*)(aph);            rAl = *(const uint4*)(apl);
        rBh0 = *(const uint4*)(hhb + bo0);     rBh1 = *(const uint4*)(hhb + bo1);
        rBl0 = *(const uint4*)(hlb + bo0);     rBl1 = *(const uint4*)(hlb + bo1);

        for (int c = 0; c < 16; c++) {
            __syncthreads();
            *(uint4*)&sAh[sA] = rAh;   *(uint4*)&sAl[sA] = rAl;
            *(uint4*)&sBh[sB0] = rBh0; *(uint4*)&sBh[sB1] = rBh1;
            *(uint4*)&sBl[sB0] = rBl0; *(uint4*)&sBl[sB1] = rBl1;
            __syncthreads();
            if (c < 15) {
                const int o = (c + 1) * KC;
                rAh = *(const uint4*)(aph + o);            rAl = *(const uint4*)(apl + o);
                rBh0 = *(const uint4*)(hhb + bo0 + o);     rBh1 = *(const uint4*)(hhb + bo1 + o);
                rBl0 = *(const uint4*)(hlb + bo0 + o);     rBl1 = *(const uint4*)(hlb + bo1 + o);
            }
            WMMA_CHUNK(sAh, sAl, sBh, sBl);
        }

        REDUCE_Q(rsm);
        __syncthreads();
        if (q == 0) {
            #pragma unroll
            for (int mi = 0; mi < 2; mi++)
                #pragma unroll
                for (int ni = 0; ni < 2; ni++)
                    wmma::store_matrix_sync(gsm + (mi * 16) * GP + p * 32 + ni * 16,
                                            acc[mi][ni], GP, wmma::mem_row_major);
        }
        __syncthreads();

        // activation: lm = gate*8 + jl; gate 3 (lm>=24) uses tanh
        #pragma unroll
        for (int u = 0; u < 8; u++) {
            const int idx = tid + 256 * u;
            const int lm = idx >> 6, n = idx & 63;
            const float v = gsm[lm * GP + n] + xwr[u];
            gsm[lm * GP + n] = (lm >= 24) ? tanhf_fast(v) : sigf(v);
        }
        __syncthreads();

        // combine
        float hv[2];
        __nv_bfloat16 hh2[2], hl2[2];
        #pragma unroll
        for (int u = 0; u < 2; u++) {
            const int jl = jp + u;
            const float iv = gsm[(jl)      * GP + cn];
            const float fv = gsm[(8 + jl)  * GP + cn];
            const float ov = gsm[(16 + jl) * GP + cn];
            const float gv = gsm[(24 + jl) * GP + cn];
            const float cprev = csm[jl * GP + cn];
            const float cnew = fv * cprev + iv * gv;
            csm[jl * GP + cn] = cnew;
            const float h = ov * tanhf_fast(cnew);
            hv[u] = h;
            const __nv_bfloat16 hb = __float2bfloat16(h);
            hh2[u] = hb;
            hl2[u] = __float2bfloat16(h - __bfloat162float(hb));
        }
        *(float2*)&out[((size_t)cn * TT + t) * HH + cta * 8 + jp] = make_float2(hv[0], hv[1]);
        const int nb = (t + 1) & 1;
        *(uint32_t*)&g_hh[nb][(size_t)cn * HH + cta * 8 + jp] = *(uint32_t*)hh2;
        *(uint32_t*)&g_hl[nb][(size_t)cn * HH + cta * 8 + jp] = *(uint32_t*)hl2;

        // grid barrier
        __syncthreads();
        if (tid == 0) {
            __threadfence();
            unsigned int ticket = atomicAdd(&g_bar_count, 1);
            if (ticket == NCTA_REC - 1) {
                g_bar_count = 0;
                __threadfence();
                atomicAdd(&g_bar_gen, 1);
            } else {
                while (*(volatile unsigned int*)&g_bar_gen < (unsigned)(t + 1)) { }
            }
            __threadfence();
        }
        __syncthreads();
    }
}

// ---------------------------------------------------------------------------
extern "C" void kernel_launch(void* const* d_in, const int* in_sizes, int n_in,
                              void* d_out, int out_size)
{
    (void)in_sizes; (void)n_in; (void)out_size;
    const float* x  = (const float*)d_in[0];
    const float* h0 = (const float*)d_in[1];
    const float* Wx = (const float*)d_in[2];
    const float* Wh = (const float*)d_in[3];
    const float* b  = (const float*)d_in[4];
    float* out = (float*)d_out;

    xsplit_kernel<<<262144, 256>>>(x);
    wprep_kernel<<<dim3(128, 32), 256>>>(Wx, 0);   // -> g_WxT_hi/lo
    wprep_kernel<<<dim3(128, 32), 256>>>(Wh, 1);   // -> g_WhT_hi/lo
    init_kernel<<<256, 256>>>(h0);
    phase1_wmma<<<dim3(128, 1024), 256>>>(b);
    rec_wmma<<<NCTA_REC, 256>>>(out);
}